// round 13
// baseline (speedup 1.0000x reference)
#include <cuda_runtime.h>
#include <cuda_bf16.h>
#include <math.h>

#define SEQ 512   // b*s rows
#define DM  512
#define DF  2048
#define NCH 4     // attention j-chunks
#define JPC 64    // j per chunk

// ---------------- scratch (device globals; no allocation allowed) -----------
__device__ unsigned g_x2B[SEQ*DM/2], g_x2S[SEQ*DM/2];
__device__ float    g_q[SEQ*DM], g_k[SEQ*DM], g_v[SEQ*DM];
__device__ unsigned g_ccB[SEQ*DM/2], g_ccS[SEQ*DM/2];
__device__ float    g_y[SEQ*DM];
__device__ unsigned g_y2B[SEQ*DM/2], g_y2S[SEQ*DM/2];
__device__ unsigned g_hB[SEQ*DF/2], g_hS[SEQ*DF/2];
__device__ float    g_scrA[4*SEQ*DM];     // attn partials / ffn2 split-K partials
__device__ float    g_pml[NCH*SEQ*8*2];   // attn partial (m,l)
__device__ unsigned g_WqB[DM*DM/2], g_WqS[DM*DM/2];
__device__ unsigned g_WkB[DM*DM/2], g_WkS[DM*DM/2];
__device__ unsigned g_WvB[DM*DM/2], g_WvS[DM*DM/2];
__device__ unsigned g_WoB[DM*DM/2], g_WoS[DM*DM/2];
__device__ unsigned g_W1B[DF*DM/2], g_W1S[DF*DM/2];
__device__ unsigned g_W2B[DM*DF/2], g_W2S[DM*DF/2];

// ---------------- helpers ----------------------------------------------------
__device__ __forceinline__ unsigned packsplit(float x0, float x1, unsigned& small) {
    __nv_bfloat16 b0 = __float2bfloat16_rn(x0);
    __nv_bfloat16 b1 = __float2bfloat16_rn(x1);
    float r0 = x0 - __bfloat162float(b0);
    float r1 = x1 - __bfloat162float(b1);
    __nv_bfloat16 s0 = __float2bfloat16_rn(r0);
    __nv_bfloat16 s1 = __float2bfloat16_rn(r1);
    small = (unsigned)__bfloat16_as_ushort(s0) |
            ((unsigned)__bfloat16_as_ushort(s1) << 16);
    return (unsigned)__bfloat16_as_ushort(b0) |
           ((unsigned)__bfloat16_as_ushort(b1) << 16);
}

__device__ __forceinline__ void mma_bf16(float c[4],
                                         unsigned a0, unsigned a1, unsigned a2, unsigned a3,
                                         unsigned b0, unsigned b1) {
    asm volatile(
        "mma.sync.aligned.m16n8k16.row.col.f32.bf16.bf16.f32 "
        "{%0,%1,%2,%3}, {%4,%5,%6,%7}, {%8,%9}, {%0,%1,%2,%3};"
        : "+f"(c[0]), "+f"(c[1]), "+f"(c[2]), "+f"(c[3])
        : "r"(a0), "r"(a1), "r"(a2), "r"(a3), "r"(b0), "r"(b1));
}

// ---------------- LayerNorm body (ddof=1), packed split output ---------------
__device__ __forceinline__ void ln_body(
    int row, int t, const float* __restrict__ x,
    const float* __restrict__ alpha, const float* __restrict__ beta,
    unsigned* __restrict__ outB, unsigned* __restrict__ outS) {
    float2 v = ((const float2*)(x + (size_t)row * 512))[t];
    float s = v.x + v.y;
    float q = v.x * v.x + v.y * v.y;
    __shared__ float ssum[8], ssq[8];
#pragma unroll
    for (int off = 16; off; off >>= 1) {
        s += __shfl_xor_sync(~0u, s, off);
        q += __shfl_xor_sync(~0u, q, off);
    }
    int w = t >> 5, l = t & 31;
    if (l == 0) { ssum[w] = s; ssq[w] = q; }
    __syncthreads();
    float tot = 0.f, totq = 0.f;
#pragma unroll
    for (int i = 0; i < 8; i++) { tot += ssum[i]; totq += ssq[i]; }
    float mu  = tot * (1.0f / 512.0f);
    float var = (totq - 512.0f * mu * mu) * (1.0f / 511.0f);
    float inv = 1.0f / (sqrtf(var) + 1e-6f);
    float2 a  = ((const float2*)alpha)[t];
    float2 bb = ((const float2*)beta)[t];
    float ox = a.x * (v.x - mu) * inv + bb.x;
    float oy = a.y * (v.y - mu) * inv + bb.y;
    unsigned sm;
    unsigned bg = packsplit(ox, oy, sm);
    outB[row * 256 + t] = bg;
    outS[row * 256 + t] = sm;
}

// ---------------- prep: weight splitting + LN1 in one launch ----------------
// blocks [0,1536): weight split (float8 per thread). blocks [1536,2048): LN1.
__global__ __launch_bounds__(256) void prep_kernel(
    const float* __restrict__ Wq, const float* __restrict__ Wk,
    const float* __restrict__ Wv, const float* __restrict__ Wo,
    const float* __restrict__ W1, const float* __restrict__ W2,
    const float* __restrict__ x, const float* __restrict__ alpha1,
    const float* __restrict__ beta1) {
    if (blockIdx.x >= 1536) {
        ln_body(blockIdx.x - 1536, threadIdx.x, x, alpha1, beta1, g_x2B, g_x2S);
        return;
    }
    int i = blockIdx.x * 256 + threadIdx.x;   // float8 index
    const int S8 = 32768, L8 = 131072;
    const float* src; unsigned* dB; unsigned* dS; int o;
    if (i < 4 * S8) {
        int w = i >> 15; o = i & 32767;
        src = (w == 0) ? Wq : (w == 1) ? Wk : (w == 2) ? Wv : Wo;
        dB  = (w == 0) ? g_WqB : (w == 1) ? g_WkB : (w == 2) ? g_WvB : g_WoB;
        dS  = (w == 0) ? g_WqS : (w == 1) ? g_WkS : (w == 2) ? g_WvS : g_WoS;
    } else if (i < 4 * S8 + L8) {
        o = i - 4 * S8; src = W1; dB = g_W1B; dS = g_W1S;
    } else {
        o = i - 4 * S8 - L8; src = W2; dB = g_W2B; dS = g_W2S;
    }
    float4 v0 = ((const float4*)src)[o * 2];
    float4 v1 = ((const float4*)src)[o * 2 + 1];
    uint4 big, sml;
    big.x = packsplit(v0.x, v0.y, sml.x);
    big.y = packsplit(v0.z, v0.w, sml.y);
    big.z = packsplit(v1.x, v1.y, sml.z);
    big.w = packsplit(v1.z, v1.w, sml.w);
    ((uint4*)dB)[o] = big;
    ((uint4*)dS)[o] = sml;
}

__global__ __launch_bounds__(256) void ln_split_kernel(
    const float* __restrict__ x, const float* __restrict__ alpha,
    const float* __restrict__ beta, unsigned* __restrict__ outB,
    unsigned* __restrict__ outS) {
    ln_body(blockIdx.x, threadIdx.x, x, alpha, beta, outB, outS);
}

// ---------------- 3x-split-BF16 GEMM, double-buffered ------------------------
// C tile = A[32 rows] @ B[64 rows]^T, strides in bf16x2 words.
__device__ __forceinline__ void gemm_body(
    const unsigned* __restrict__ AB, const unsigned* __restrict__ AS,
    const unsigned* __restrict__ BB, const unsigned* __restrict__ BS,
    const float* __restrict__ bias, const float* __restrict__ Res,
    float* __restrict__ C, unsigned* __restrict__ CB, unsigned* __restrict__ CS,
    int N, int ldaW, int ldbW, int kWords, int relu) {
    __shared__ unsigned sAB[2][32][20], sAS[2][32][20];
    __shared__ unsigned sBB[2][64][20], sBS[2][64][20];
    int tid = threadIdx.x;
    int m0 = blockIdx.y * 32, n0 = blockIdx.x * 64;
    int ra = tid >> 2, ca = (tid & 3) * 4;
    int rb = tid >> 1, cb = (tid & 1) * 8;
    const unsigned* pAB = AB + (size_t)(m0 + ra) * ldaW + ca;
    const unsigned* pAS = AS + (size_t)(m0 + ra) * ldaW + ca;
    const unsigned* pBB = BB + (size_t)(n0 + rb) * ldbW + cb;
    const unsigned* pBS = BS + (size_t)(n0 + rb) * ldbW + cb;

    int w = tid >> 5, lane = tid & 31;
    int g = lane >> 2, tg = lane & 3;

    float acc[2][2][4] = {};

    uint4 rA_B, rA_S, rB_B[2], rB_S[2];
    rA_B = *(const uint4*)pAB;
    rA_S = *(const uint4*)pAS;
    rB_B[0] = *(const uint4*)pBB; rB_B[1] = *(const uint4*)(pBB + 4);
    rB_S[0] = *(const uint4*)pBS; rB_S[1] = *(const uint4*)(pBS + 4);

    int nst = kWords >> 4;
    for (int st = 0; st < nst; st++) {
        int cur = st & 1;
        *(uint4*)&sAB[cur][ra][ca] = rA_B;
        *(uint4*)&sAS[cur][ra][ca] = rA_S;
        *(uint4*)&sBB[cur][rb][cb] = rB_B[0]; *(uint4*)&sBB[cur][rb][cb + 4] = rB_B[1];
        *(uint4*)&sBS[cur][rb][cb] = rB_S[0]; *(uint4*)&sBS[cur][rb][cb + 4] = rB_S[1];
        __syncthreads();
        if (st + 1 < nst) {
            pAB += 16; pAS += 16; pBB += 16; pBS += 16;
            rA_B = *(const uint4*)pAB;
            rA_S = *(const uint4*)pAS;
            rB_B[0] = *(const uint4*)pBB; rB_B[1] = *(const uint4*)(pBB + 4);
            rB_S[0] = *(const uint4*)pBS; rB_S[1] = *(const uint4*)(pBS + 4);
        }
#pragma unroll
        for (int s = 0; s < 16; s += 8) {
            unsigned aB[2][4], aS[2][4], bB[2][2], bS[2][2];
#pragma unroll
            for (int mt = 0; mt < 2; mt++) {
                int r0 = mt * 16 + g;
                aB[mt][0] = sAB[cur][r0][s + tg];
                aB[mt][1] = sAB[cur][r0 + 8][s + tg];
                aB[mt][2] = sAB[cur][r0][s + tg + 4];
                aB[mt][3] = sAB[cur][r0 + 8][s + tg + 4];
                aS[mt][0] = sAS[cur][r0][s + tg];
                aS[mt][1] = sAS[cur][r0 + 8][s + tg];
                aS[mt][2] = sAS[cur][r0][s + tg + 4];
                aS[mt][3] = sAS[cur][r0 + 8][s + tg + 4];
            }
#pragma unroll
            for (int nt = 0; nt < 2; nt++) {
                int c0 = w * 16 + nt * 8 + g;
                bB[nt][0] = sBB[cur][c0][s + tg];
                bB[nt][1] = sBB[cur][c0][s + tg + 4];
                bS[nt][0] = sBS[cur][c0][s + tg];
                bS[nt][1] = sBS[cur][c0][s + tg + 4];
            }
#pragma unroll
            for (int mt = 0; mt < 2; mt++)
#pragma unroll
                for (int nt = 0; nt < 2; nt++) {
                    mma_bf16(acc[mt][nt], aB[mt][0], aB[mt][1], aB[mt][2], aB[mt][3],
                             bB[nt][0], bB[nt][1]);
                    mma_bf16(acc[mt][nt], aB[mt][0], aB[mt][1], aB[mt][2], aB[mt][3],
                             bS[nt][0], bS[nt][1]);
                    mma_bf16(acc[mt][nt], aS[mt][0], aS[mt][1], aS[mt][2], aS[mt][3],
                             bB[nt][0], bB[nt][1]);
                }
        }
    }
    int NW = N >> 1;
#pragma unroll
    for (int mt = 0; mt < 2; mt++)
#pragma unroll
        for (int nt = 0; nt < 2; nt++) {
            int row = m0 + mt * 16 + g;
            int col = n0 + w * 16 + nt * 8 + tg * 2;
            float2 bz = bias ? *(const float2*)(bias + col) : make_float2(0.f, 0.f);
#pragma unroll
            for (int h = 0; h < 2; h++) {
                int rr = row + h * 8;
                float cx = acc[mt][nt][h * 2 + 0] + bz.x;
                float cy = acc[mt][nt][h * 2 + 1] + bz.y;
                if (relu) { cx = fmaxf(cx, 0.f); cy = fmaxf(cy, 0.f); }
                if (Res) {
                    float2 rv = *(const float2*)(Res + (size_t)rr * N + col);
                    cx += rv.x; cy += rv.y;
                }
                if (C)
                    *(float2*)(C + (size_t)rr * N + col) = make_float2(cx, cy);
                if (CB) {
                    unsigned sm;
                    unsigned bg = packsplit(cx, cy, sm);
                    CB[(size_t)rr * NW + (col >> 1)] = bg;
                    CS[(size_t)rr * NW + (col >> 1)] = sm;
                }
            }
        }
}

// QKV: no split-K, bias in epilogue, direct write. grid (8,16,3).
__global__ __launch_bounds__(128) void gemm_qkv_kernel(
    const float* __restrict__ bq, const float* __restrict__ bk,
    const float* __restrict__ bv) {
    int proj = blockIdx.z;
    const unsigned *BB, *BS; const float* bias; float* C;
    if (proj == 0)      { BB = g_WqB; BS = g_WqS; bias = bq; C = g_q; }
    else if (proj == 1) { BB = g_WkB; BS = g_WkS; bias = bk; C = g_k; }
    else                { BB = g_WvB; BS = g_WvS; bias = bv; C = g_v; }
    gemm_body(g_x2B, g_x2S, BB, BS, bias, nullptr, C, nullptr, nullptr,
              512, 256, 256, 256, 0);
}

// Wo: no split-K; epilogue adds bias + residual(x), writes y. grid (8,16).
__global__ __launch_bounds__(128) void gemm_wo_kernel(
    const float* __restrict__ bo, const float* __restrict__ x) {
    gemm_body(g_ccB, g_ccS, g_WoB, g_WoS, bo, x, g_y, nullptr, nullptr,
              512, 256, 256, 256, 0);
}

__global__ __launch_bounds__(128) void gemm_ffn1_kernel(
    const float* __restrict__ b1) {
    gemm_body(g_y2B, g_y2S, g_W1B, g_W1S, b1, nullptr, nullptr, g_hB, g_hS,
              2048, 256, 256, 256, 1);
}

// FFN2 split-K=4 (K=2048: split needed to fill the chip; reduce is the
// mandatory bias+residual output writer anyway)
__global__ __launch_bounds__(128) void gemm_ffn2_part_kernel() {
    int s = blockIdx.z;
    gemm_body(g_hB + s * 256, g_hS + s * 256,
              g_W2B + s * 256, g_W2S + s * 256,
              nullptr, nullptr, g_scrA + (size_t)s * SEQ * DM, nullptr, nullptr,
              512, 1024, 1024, 256, 0);
}

__global__ __launch_bounds__(128) void ffn2_reduce_kernel(
    const float* __restrict__ b2, float* __restrict__ out) {
    int idx = blockIdx.x * 128 + threadIdx.x;
    int row = idx >> 7, c4 = (idx & 127) * 4;
    size_t o = (size_t)row * 512 + c4;
    float4 a0 = *(const float4*)(g_scrA + o);
    float4 a1 = *(const float4*)(g_scrA + SEQ * DM + o);
    float4 a2 = *(const float4*)(g_scrA + 2 * SEQ * DM + o);
    float4 a3 = *(const float4*)(g_scrA + (size_t)3 * SEQ * DM + o);
    float4 bz = *(const float4*)(b2 + c4);
    float4 rv = *(const float4*)(g_y + o);
    float4 r;
    r.x = a0.x + a1.x + a2.x + a3.x + bz.x + rv.x;
    r.y = a0.y + a1.y + a2.y + a3.y + bz.y + rv.y;
    r.z = a0.z + a1.z + a2.z + a3.z + bz.z + rv.z;
    r.w = a0.w + a1.w + a2.w + a3.w + bz.w + rv.w;
    *(float4*)(out + o) = r;
}

// ---------------- attention: 3-phase split-j partial pass --------------------
__global__ __launch_bounds__(128, 10) void attn_part_kernel(
    const float* __restrict__ cbk, const float* __restrict__ cbv,
    const int* __restrict__ mask) {
    int bi = blockIdx.x;
    int ch = blockIdx.y;
    int b = bi >> 8, i = bi & 255;
    int tid = threadIdx.x;
    int w = tid >> 5, lane = tid & 31;
    int h = (w << 1) + (lane >> 4);
    int l16 = lane & 15;
    int d0 = (h << 6) + (l16 << 2);

    __shared__ float mb[JPC];
    __shared__ float sp[8][JPC];
    if (tid < JPC)
        mb[tid] = (mask[(b << 8) + ch * JPC + tid] == 1) ? -1e9f : 0.0f;
    __syncthreads();

    const float4 q4 = *(const float4*)(g_q + ((size_t)bi << 9) + d0);
    const float* kp = g_k + (((size_t)b << 8) << 9) + d0;
    const float* vp = g_v + (((size_t)b << 8) << 9) + d0;
    const size_t cb_base = (size_t)b * 33554432 + (size_t)i * 512 + d0;
    const float* ckp = cbk + cb_base;
    const float* cvp = cbv + cb_base;
    int jbase = ch * JPC;

    // ---- phase 1: raw scores (cb stream: evict-first, single-use) ----
    for (int j0 = 0; j0 < JPC; j0 += 4) {
        float s[4];
#pragma unroll
        for (int u = 0; u < 4; u++) {
            size_t j = (size_t)(jbase + j0 + u);
            float4 kk = *(const float4*)(kp + j * 512);
            float4 ck = __ldcs((const float4*)(ckp + j * 131072));
            s[u] = q4.x * kk.x + q4.y * kk.y + q4.z * kk.z + q4.w * kk.w
                 + q4.x * ck.x + q4.y * ck.y + q4.z * ck.z + q4.w * ck.w;
        }
#pragma unroll
        for (int off = 8; off; off >>= 1) {
#pragma unroll
            for (int u = 0; u < 4; u++) s[u] += __shfl_xor_sync(~0u, s[u], off);
        }
        if (l16 == 0) {
#pragma unroll
            for (int u = 0; u < 4; u++) sp[h][j0 + u] = s[u];
        }
    }
    __syncwarp();

    // ---- phase 2: softmax over this chunk ----
    int jm = l16 * 4;
    float sc[4];
#pragma unroll
    for (int t = 0; t < 4; t++)
        sc[t] = sp[h][jm + t] * 0.125f + mb[jm + t];
    float m4 = fmaxf(fmaxf(sc[0], sc[1]), fmaxf(sc[2], sc[3]));
#pragma unroll
    for (int off = 8; off; off >>= 1)
        m4 = fmaxf(m4, __shfl_xor_sync(~0u, m4, off));
    float p[4], l4 = 0.f;
#pragma unroll
    for (int t = 0; t < 4; t++) {
        p[t] = __expf(sc[t] - m4);
        l4 += p[t];
    }
#pragma unroll
    for (int off = 8; off; off >>= 1)
        l4 += __shfl_xor_sync(~0u, l4, off);
#pragma unroll
    for (int t = 0; t < 4; t++) sp[h][jm + t] = p[t];
    __syncwarp();

    // ---- phase 3: PV accumulation ----
    float4 acc = make_float4(0.f, 0.f, 0.f, 0.f);
    for (int j0 = 0; j0 < JPC; j0 += 4) {
#pragma unroll
        for (int u = 0; u < 4; u++) {
            size_t j = (size_t)(jbase + j0 + u);
            float4 vv = *(const float4*)(vp + j * 512);
            float4 cv = __ldcs((const float4*)(cvp + j * 131072));
            float pj = sp[h][j0 + u];
            acc.x += pj * (vv.x + cv.x);
            acc.y += pj * (vv.y + cv.y);
            acc.z += pj * (vv.z + cv.z);
            acc.w += pj * (vv.w + cv.w);
        }
    }
    *(float4*)(g_scrA + ((size_t)(ch * SEQ + bi) << 9) + d0) = acc;
    if (l16 == 0)
        *(float2*)(g_pml + ((size_t)(ch * SEQ + bi) * 8 + h) * 2) = make_float2(m4, l4);
}

// combine 4 chunk partials -> packed split concat planes
__global__ __launch_bounds__(128) void attn_combine_kernel() {
    int bi = blockIdx.x;
    int t = threadIdx.x;
    int d0 = t << 2;
    int h = d0 >> 6;
    float mm[NCH], ll[NCH];
    float M = -INFINITY;
#pragma unroll
    for (int c = 0; c < NCH; c++) {
        float2 ml = *(const float2*)(g_pml + ((size_t)(c * SEQ + bi) * 8 + h) * 2);
        mm[c] = ml.x; ll[c] = ml.y;
        M = fmaxf(M, ml.x);
    }
    float L = 0.f;
    float4 a = make_float4(0.f, 0.f, 0.f, 0.f);
#pragma unroll
    for (int c = 0; c < NCH; c++) {
        float wgt = __expf(mm[c] - M);
        L += ll[c] * wgt;
        float4 p = *(const float4*)(g_scrA + ((size_t)(c * SEQ + bi) << 9) + d0);
        a.x += p.x * wgt; a.y += p.y * wgt; a.z += p.z * wgt; a.w += p.w * wgt;
    }
    float inv = 1.0f / L;
    float o0 = a.x * inv, o1 = a.y * inv, o2 = a.z * inv, o3 = a.w * inv;
    unsigned s0, s1;
    unsigned b0 = packsplit(o0, o1, s0);
    unsigned b1 = packsplit(o2, o3, s1);
    size_t ow = (size_t)bi * 256 + (d0 >> 1);
    g_ccB[ow] = b0; g_ccB[ow + 1] = b1;
    g_ccS[ow] = s0; g_ccS[ow + 1] = s1;
}

// ---------------- launch ----------------------------------------------------
extern "C" void kernel_launch(void* const* d_in, const int* in_sizes, int n_in,
                              void* d_out, int out_size) {
    const float* x    = (const float*)d_in[0];
    const float* cbk  = (const float*)d_in[1];
    const float* cbv  = (const float*)d_in[2];
    const int*   mask = (const int*)d_in[3];
    const float* Wq = (const float*)d_in[4];
    const float* bq = (const float*)d_in[5];
    const float* Wk = (const float*)d_in[6];
    const float* bk = (const float*)d_in[7];
    const float* Wv = (const float*)d_in[8];
    const float* bv = (const float*)d_in[9];
    const float* Wo = (const float*)d_in[10];
    const float* bo = (const float*)d_in[11];
    const float* alpha1 = (const float*)d_in[12];
    const float* beta1  = (const float*)d_in[13];
    const float* alpha2 = (const float*)d_in[14];
    const float* beta2  = (const float*)d_in[15];
    const float* W1 = (const float*)d_in[16];
    const float* b1 = (const float*)d_in[17];
    const float* W2 = (const float*)d_in[18];
    const float* b2 = (const float*)d_in[19];
    float* out = (float*)d_out;

    unsigned *pyB, *pyS;
    float *py;
    cudaGetSymbolAddress((void**)&pyB, g_y2B);
    cudaGetSymbolAddress((void**)&pyS, g_y2S);
    cudaGetSymbolAddress((void**)&py,  g_y);

    // 1) prep: weight split + LN1 (one launch)
    prep_kernel<<<2048, 256>>>(Wq, Wk, Wv, Wo, W1, W2, x, alpha1, beta1);
    // 2) QKV projections, direct write with bias (384 CTAs)
    gemm_qkv_kernel<<<dim3(8, 16, 3), 128>>>(bq, bk, bv);
    // 3) attention: 4-way split-j 3-phase partials + combine
    attn_part_kernel<<<dim3(512, NCH), 128>>>(cbk, cbv, mask);
    attn_combine_kernel<<<512, 128>>>();
    // 4) Wo + bias + residual(x) -> y
    gemm_wo_kernel<<<dim3(8, 16), 128>>>(bo, x);
    // 5) LN2 -> packed split y2
    ln_split_kernel<<<512, 256>>>(py, alpha2, beta2, pyB, pyS);
    // 6) FFN up + ReLU -> packed split h
    gemm_ffn1_kernel<<<dim3(32, 16), 128>>>(b1);
    // 7) FFN down split-K=4 + reduce(+bias+residual) -> out
    gemm_ffn2_part_kernel<<<dim3(8, 16, 4), 128>>>();
    ffn2_reduce_kernel<<<512, 128>>>(b2, out);
}

// round 14
// speedup vs baseline: 1.0536x; 1.0536x over previous
#include <cuda_runtime.h>
#include <cuda_bf16.h>
#include <math.h>

#define SEQ 512   // b*s rows
#define DM  512
#define DF  2048
#define NCH 4     // attention j-chunks
#define JPC 64    // j per chunk

// ---------------- scratch (device globals; no allocation allowed) -----------
__device__ unsigned g_x2B[SEQ*DM/2], g_x2S[SEQ*DM/2];
__device__ float    g_q[SEQ*DM], g_k[SEQ*DM], g_v[SEQ*DM];
__device__ unsigned g_ccB[SEQ*DM/2], g_ccS[SEQ*DM/2];
__device__ float    g_y[SEQ*DM];
__device__ unsigned g_y2B[SEQ*DM/2], g_y2S[SEQ*DM/2];
__device__ unsigned g_hB[SEQ*DF/2], g_hS[SEQ*DF/2];
__device__ float    g_scrA[4*SEQ*DM];     // attn partials / ffn2 split-K partials
__device__ float    g_pml[NCH*SEQ*8*2];   // attn partial (m,l)
__device__ unsigned g_WqB[DM*DM/2], g_WqS[DM*DM/2];
__device__ unsigned g_WkB[DM*DM/2], g_WkS[DM*DM/2];
__device__ unsigned g_WvB[DM*DM/2], g_WvS[DM*DM/2];
__device__ unsigned g_WoB[DM*DM/2], g_WoS[DM*DM/2];
__device__ unsigned g_W1B[DF*DM/2], g_W1S[DF*DM/2];
__device__ unsigned g_W2B[DM*DF/2], g_W2S[DM*DF/2];

// ---------------- helpers ----------------------------------------------------
__device__ __forceinline__ unsigned packsplit(float x0, float x1, unsigned& small) {
    __nv_bfloat16 b0 = __float2bfloat16_rn(x0);
    __nv_bfloat16 b1 = __float2bfloat16_rn(x1);
    float r0 = x0 - __bfloat162float(b0);
    float r1 = x1 - __bfloat162float(b1);
    __nv_bfloat16 s0 = __float2bfloat16_rn(r0);
    __nv_bfloat16 s1 = __float2bfloat16_rn(r1);
    small = (unsigned)__bfloat16_as_ushort(s0) |
            ((unsigned)__bfloat16_as_ushort(s1) << 16);
    return (unsigned)__bfloat16_as_ushort(b0) |
           ((unsigned)__bfloat16_as_ushort(b1) << 16);
}

__device__ __forceinline__ void mma_bf16(float c[4],
                                         unsigned a0, unsigned a1, unsigned a2, unsigned a3,
                                         unsigned b0, unsigned b1) {
    asm volatile(
        "mma.sync.aligned.m16n8k16.row.col.f32.bf16.bf16.f32 "
        "{%0,%1,%2,%3}, {%4,%5,%6,%7}, {%8,%9}, {%0,%1,%2,%3};"
        : "+f"(c[0]), "+f"(c[1]), "+f"(c[2]), "+f"(c[3])
        : "r"(a0), "r"(a1), "r"(a2), "r"(a3), "r"(b0), "r"(b1));
}

// ---------------- LayerNorm body (ddof=1), packed split output ---------------
__device__ __forceinline__ void ln_body(
    int row, int t, const float* __restrict__ x,
    const float* __restrict__ alpha, const float* __restrict__ beta,
    unsigned* __restrict__ outB, unsigned* __restrict__ outS) {
    float2 v = ((const float2*)(x + (size_t)row * 512))[t];
    float s = v.x + v.y;
    float q = v.x * v.x + v.y * v.y;
    __shared__ float ssum[8], ssq[8];
#pragma unroll
    for (int off = 16; off; off >>= 1) {
        s += __shfl_xor_sync(~0u, s, off);
        q += __shfl_xor_sync(~0u, q, off);
    }
    int w = t >> 5, l = t & 31;
    if (l == 0) { ssum[w] = s; ssq[w] = q; }
    __syncthreads();
    float tot = 0.f, totq = 0.f;
#pragma unroll
    for (int i = 0; i < 8; i++) { tot += ssum[i]; totq += ssq[i]; }
    float mu  = tot * (1.0f / 512.0f);
    float var = (totq - 512.0f * mu * mu) * (1.0f / 511.0f);
    float inv = 1.0f / (sqrtf(var) + 1e-6f);
    float2 a  = ((const float2*)alpha)[t];
    float2 bb = ((const float2*)beta)[t];
    float ox = a.x * (v.x - mu) * inv + bb.x;
    float oy = a.y * (v.y - mu) * inv + bb.y;
    unsigned sm;
    unsigned bg = packsplit(ox, oy, sm);
    outB[row * 256 + t] = bg;
    outS[row * 256 + t] = sm;
}

// ---------------- prep: weight splitting + LN1 in one launch ----------------
__global__ __launch_bounds__(256) void prep_kernel(
    const float* __restrict__ Wq, const float* __restrict__ Wk,
    const float* __restrict__ Wv, const float* __restrict__ Wo,
    const float* __restrict__ W1, const float* __restrict__ W2,
    const float* __restrict__ x, const float* __restrict__ alpha1,
    const float* __restrict__ beta1) {
    if (blockIdx.x >= 1536) {
        ln_body(blockIdx.x - 1536, threadIdx.x, x, alpha1, beta1, g_x2B, g_x2S);
        return;
    }
    int i = blockIdx.x * 256 + threadIdx.x;   // float8 index
    const int S8 = 32768, L8 = 131072;
    const float* src; unsigned* dB; unsigned* dS; int o;
    if (i < 4 * S8) {
        int w = i >> 15; o = i & 32767;
        src = (w == 0) ? Wq : (w == 1) ? Wk : (w == 2) ? Wv : Wo;
        dB  = (w == 0) ? g_WqB : (w == 1) ? g_WkB : (w == 2) ? g_WvB : g_WoB;
        dS  = (w == 0) ? g_WqS : (w == 1) ? g_WkS : (w == 2) ? g_WvS : g_WoS;
    } else if (i < 4 * S8 + L8) {
        o = i - 4 * S8; src = W1; dB = g_W1B; dS = g_W1S;
    } else {
        o = i - 4 * S8 - L8; src = W2; dB = g_W2B; dS = g_W2S;
    }
    float4 v0 = ((const float4*)src)[o * 2];
    float4 v1 = ((const float4*)src)[o * 2 + 1];
    uint4 big, sml;
    big.x = packsplit(v0.x, v0.y, sml.x);
    big.y = packsplit(v0.z, v0.w, sml.y);
    big.z = packsplit(v1.x, v1.y, sml.z);
    big.w = packsplit(v1.z, v1.w, sml.w);
    ((uint4*)dB)[o] = big;
    ((uint4*)dS)[o] = sml;
}

__global__ __launch_bounds__(256) void ln_split_kernel(
    const float* __restrict__ x, const float* __restrict__ alpha,
    const float* __restrict__ beta, unsigned* __restrict__ outB,
    unsigned* __restrict__ outS) {
    ln_body(blockIdx.x, threadIdx.x, x, alpha, beta, outB, outS);
}

// ---------------- 3x-split-BF16 GEMM, double-buffered ------------------------
__device__ __forceinline__ void gemm_body(
    const unsigned* __restrict__ AB, const unsigned* __restrict__ AS,
    const unsigned* __restrict__ BB, const unsigned* __restrict__ BS,
    const float* __restrict__ bias, const float* __restrict__ Res,
    float* __restrict__ C, unsigned* __restrict__ CB, unsigned* __restrict__ CS,
    int N, int ldaW, int ldbW, int kWords, int relu) {
    __shared__ unsigned sAB[2][32][20], sAS[2][32][20];
    __shared__ unsigned sBB[2][64][20], sBS[2][64][20];
    int tid = threadIdx.x;
    int m0 = blockIdx.y * 32, n0 = blockIdx.x * 64;
    int ra = tid >> 2, ca = (tid & 3) * 4;
    int rb = tid >> 1, cb = (tid & 1) * 8;
    const unsigned* pAB = AB + (size_t)(m0 + ra) * ldaW + ca;
    const unsigned* pAS = AS + (size_t)(m0 + ra) * ldaW + ca;
    const unsigned* pBB = BB + (size_t)(n0 + rb) * ldbW + cb;
    const unsigned* pBS = BS + (size_t)(n0 + rb) * ldbW + cb;

    int w = tid >> 5, lane = tid & 31;
    int g = lane >> 2, tg = lane & 3;

    float acc[2][2][4] = {};

    uint4 rA_B, rA_S, rB_B[2], rB_S[2];
    rA_B = *(const uint4*)pAB;
    rA_S = *(const uint4*)pAS;
    rB_B[0] = *(const uint4*)pBB; rB_B[1] = *(const uint4*)(pBB + 4);
    rB_S[0] = *(const uint4*)pBS; rB_S[1] = *(const uint4*)(pBS + 4);

    int nst = kWords >> 4;
    for (int st = 0; st < nst; st++) {
        int cur = st & 1;
        *(uint4*)&sAB[cur][ra][ca] = rA_B;
        *(uint4*)&sAS[cur][ra][ca] = rA_S;
        *(uint4*)&sBB[cur][rb][cb] = rB_B[0]; *(uint4*)&sBB[cur][rb][cb + 4] = rB_B[1];
        *(uint4*)&sBS[cur][rb][cb] = rB_S[0]; *(uint4*)&sBS[cur][rb][cb + 4] = rB_S[1];
        __syncthreads();
        if (st + 1 < nst) {
            pAB += 16; pAS += 16; pBB += 16; pBS += 16;
            rA_B = *(const uint4*)pAB;
            rA_S = *(const uint4*)pAS;
            rB_B[0] = *(const uint4*)pBB; rB_B[1] = *(const uint4*)(pBB + 4);
            rB_S[0] = *(const uint4*)pBS; rB_S[1] = *(const uint4*)(pBS + 4);
        }
#pragma unroll
        for (int s = 0; s < 16; s += 8) {
            unsigned aB[2][4], aS[2][4], bB[2][2], bS[2][2];
#pragma unroll
            for (int mt = 0; mt < 2; mt++) {
                int r0 = mt * 16 + g;
                aB[mt][0] = sAB[cur][r0][s + tg];
                aB[mt][1] = sAB[cur][r0 + 8][s + tg];
                aB[mt][2] = sAB[cur][r0][s + tg + 4];
                aB[mt][3] = sAB[cur][r0 + 8][s + tg + 4];
                aS[mt][0] = sAS[cur][r0][s + tg];
                aS[mt][1] = sAS[cur][r0 + 8][s + tg];
                aS[mt][2] = sAS[cur][r0][s + tg + 4];
                aS[mt][3] = sAS[cur][r0 + 8][s + tg + 4];
            }
#pragma unroll
            for (int nt = 0; nt < 2; nt++) {
                int c0 = w * 16 + nt * 8 + g;
                bB[nt][0] = sBB[cur][c0][s + tg];
                bB[nt][1] = sBB[cur][c0][s + tg + 4];
                bS[nt][0] = sBS[cur][c0][s + tg];
                bS[nt][1] = sBS[cur][c0][s + tg + 4];
            }
#pragma unroll
            for (int mt = 0; mt < 2; mt++)
#pragma unroll
                for (int nt = 0; nt < 2; nt++) {
                    mma_bf16(acc[mt][nt], aB[mt][0], aB[mt][1], aB[mt][2], aB[mt][3],
                             bB[nt][0], bB[nt][1]);
                    mma_bf16(acc[mt][nt], aB[mt][0], aB[mt][1], aB[mt][2], aB[mt][3],
                             bS[nt][0], bS[nt][1]);
                    mma_bf16(acc[mt][nt], aS[mt][0], aS[mt][1], aS[mt][2], aS[mt][3],
                             bB[nt][0], bB[nt][1]);
                }
        }
    }
    int NW = N >> 1;
#pragma unroll
    for (int mt = 0; mt < 2; mt++)
#pragma unroll
        for (int nt = 0; nt < 2; nt++) {
            int row = m0 + mt * 16 + g;
            int col = n0 + w * 16 + nt * 8 + tg * 2;
            float2 bz = bias ? *(const float2*)(bias + col) : make_float2(0.f, 0.f);
#pragma unroll
            for (int h = 0; h < 2; h++) {
                int rr = row + h * 8;
                float cx = acc[mt][nt][h * 2 + 0] + bz.x;
                float cy = acc[mt][nt][h * 2 + 1] + bz.y;
                if (relu) { cx = fmaxf(cx, 0.f); cy = fmaxf(cy, 0.f); }
                if (Res) {
                    float2 rv = *(const float2*)(Res + (size_t)rr * N + col);
                    cx += rv.x; cy += rv.y;
                }
                if (C)
                    *(float2*)(C + (size_t)rr * N + col) = make_float2(cx, cy);
                if (CB) {
                    unsigned sm;
                    unsigned bg = packsplit(cx, cy, sm);
                    CB[(size_t)rr * NW + (col >> 1)] = bg;
                    CS[(size_t)rr * NW + (col >> 1)] = sm;
                }
            }
        }
}

// QKV: no split-K, bias in epilogue, direct write. grid (8,16,3).
__global__ __launch_bounds__(128) void gemm_qkv_kernel(
    const float* __restrict__ bq, const float* __restrict__ bk,
    const float* __restrict__ bv) {
    int proj = blockIdx.z;
    const unsigned *BB, *BS; const float* bias; float* C;
    if (proj == 0)      { BB = g_WqB; BS = g_WqS; bias = bq; C = g_q; }
    else if (proj == 1) { BB = g_WkB; BS = g_WkS; bias = bk; C = g_k; }
    else                { BB = g_WvB; BS = g_WvS; bias = bv; C = g_v; }
    gemm_body(g_x2B, g_x2S, BB, BS, bias, nullptr, C, nullptr, nullptr,
              512, 256, 256, 256, 0);
}

// Wo: no split-K; epilogue adds bias + residual(x), writes y. grid (8,16).
__global__ __launch_bounds__(128) void gemm_wo_kernel(
    const float* __restrict__ bo, const float* __restrict__ x) {
    gemm_body(g_ccB, g_ccS, g_WoB, g_WoS, bo, x, g_y, nullptr, nullptr,
              512, 256, 256, 256, 0);
}

__global__ __launch_bounds__(128) void gemm_ffn1_kernel(
    const float* __restrict__ b1) {
    gemm_body(g_y2B, g_y2S, g_W1B, g_W1S, b1, nullptr, nullptr, g_hB, g_hS,
              2048, 256, 256, 256, 1);
}

// FFN2 split-K=4
__global__ __launch_bounds__(128) void gemm_ffn2_part_kernel() {
    int s = blockIdx.z;
    gemm_body(g_hB + s * 256, g_hS + s * 256,
              g_W2B + s * 256, g_W2S + s * 256,
              nullptr, nullptr, g_scrA + (size_t)s * SEQ * DM, nullptr, nullptr,
              512, 1024, 1024, 256, 0);
}

__global__ __launch_bounds__(128) void ffn2_reduce_kernel(
    const float* __restrict__ b2, float* __restrict__ out) {
    int idx = blockIdx.x * 128 + threadIdx.x;
    int row = idx >> 7, c4 = (idx & 127) * 4;
    size_t o = (size_t)row * 512 + c4;
    float4 a0 = *(const float4*)(g_scrA + o);
    float4 a1 = *(const float4*)(g_scrA + SEQ * DM + o);
    float4 a2 = *(const float4*)(g_scrA + 2 * SEQ * DM + o);
    float4 a3 = *(const float4*)(g_scrA + (size_t)3 * SEQ * DM + o);
    float4 bz = *(const float4*)(b2 + c4);
    float4 rv = *(const float4*)(g_y + o);
    float4 r;
    r.x = a0.x + a1.x + a2.x + a3.x + bz.x + rv.x;
    r.y = a0.y + a1.y + a2.y + a3.y + bz.y + rv.y;
    r.z = a0.z + a1.z + a2.z + a3.z + bz.z + rv.z;
    r.w = a0.w + a1.w + a2.w + a3.w + bz.w + rv.w;
    *(float4*)(out + o) = r;
}

// ---------------- attention: 3-phase split-j partial pass --------------------
// (128,8): proven config — 56 regs, no spills, occ ~47%, DRAM 82%
__global__ __launch_bounds__(128, 8) void attn_part_kernel(
    const float* __restrict__ cbk, const float* __restrict__ cbv,
    const int* __restrict__ mask) {
    int bi = blockIdx.x;
    int ch = blockIdx.y;
    int b = bi >> 8, i = bi & 255;
    int tid = threadIdx.x;
    int w = tid >> 5, lane = tid & 31;
    int h = (w << 1) + (lane >> 4);
    int l16 = lane & 15;
    int d0 = (h << 6) + (l16 << 2);

    __shared__ float mb[JPC];
    __shared__ float sp[8][JPC];
    if (tid < JPC)
        mb[tid] = (mask[(b << 8) + ch * JPC + tid] == 1) ? -1e9f : 0.0f;
    __syncthreads();

    const float4 q4 = *(const float4*)(g_q + ((size_t)bi << 9) + d0);
    const float* kp = g_k + (((size_t)b << 8) << 9) + d0;
    const float* vp = g_v + (((size_t)b << 8) << 9) + d0;
    const size_t cb_base = (size_t)b * 33554432 + (size_t)i * 512 + d0;
    const float* ckp = cbk + cb_base;
    const float* cvp = cbv + cb_base;
    int jbase = ch * JPC;

    // ---- phase 1: raw scores (cb stream: evict-first, single-use) ----
    for (int j0 = 0; j0 < JPC; j0 += 4) {
        float s[4];
#pragma unroll
        for (int u = 0; u < 4; u++) {
            size_t j = (size_t)(jbase + j0 + u);
            float4 kk = *(const float4*)(kp + j * 512);
            float4 ck = __ldcs((const float4*)(ckp + j * 131072));
            s[u] = q4.x * kk.x + q4.y * kk.y + q4.z * kk.z + q4.w * kk.w
                 + q4.x * ck.x + q4.y * ck.y + q4.z * ck.z + q4.w * ck.w;
        }
#pragma unroll
        for (int off = 8; off; off >>= 1) {
#pragma unroll
            for (int u = 0; u < 4; u++) s[u] += __shfl_xor_sync(~0u, s[u], off);
        }
        if (l16 == 0) {
#pragma unroll
            for (int u = 0; u < 4; u++) sp[h][j0 + u] = s[u];
        }
    }
    __syncwarp();

    // ---- phase 2: softmax over this chunk ----
    int jm = l16 * 4;
    float sc[4];
#pragma unroll
    for (int t = 0; t < 4; t++)
        sc[t] = sp[h][jm + t] * 0.125f + mb[jm + t];
    float m4 = fmaxf(fmaxf(sc[0], sc[1]), fmaxf(sc[2], sc[3]));
#pragma unroll
    for (int off = 8; off; off >>= 1)
        m4 = fmaxf(m4, __shfl_xor_sync(~0u, m4, off));
    float p[4], l4 = 0.f;
#pragma unroll
    for (int t = 0; t < 4; t++) {
        p[t] = __expf(sc[t] - m4);
        l4 += p[t];
    }
#pragma unroll
    for (int off = 8; off; off >>= 1)
        l4 += __shfl_xor_sync(~0u, l4, off);
#pragma unroll
    for (int t = 0; t < 4; t++) sp[h][jm + t] = p[t];
    __syncwarp();

    // ---- phase 3: PV accumulation ----
    float4 acc = make_float4(0.f, 0.f, 0.f, 0.f);
    for (int j0 = 0; j0 < JPC; j0 += 4) {
#pragma unroll
        for (int u = 0; u < 4; u++) {
            size_t j = (size_t)(jbase + j0 + u);
            float4 vv = *(const float4*)(vp + j * 512);
            float4 cv = __ldcs((const float4*)(cvp + j * 131072));
            float pj = sp[h][j0 + u];
            acc.x += pj * (vv.x + cv.x);
            acc.y += pj * (vv.y + cv.y);
            acc.z += pj * (vv.z + cv.z);
            acc.w += pj * (vv.w + cv.w);
        }
    }
    *(float4*)(g_scrA + ((size_t)(ch * SEQ + bi) << 9) + d0) = acc;
    if (l16 == 0)
        *(float2*)(g_pml + ((size_t)(ch * SEQ + bi) * 8 + h) * 2) = make_float2(m4, l4);
}

// combine 4 chunk partials -> packed split concat planes
__global__ __launch_bounds__(128) void attn_combine_kernel() {
    int bi = blockIdx.x;
    int t = threadIdx.x;
    int d0 = t << 2;
    int h = d0 >> 6;
    float mm[NCH], ll[NCH];
    float M = -INFINITY;
#pragma unroll
    for (int c = 0; c < NCH; c++) {
        float2 ml = *(const float2*)(g_pml + ((size_t)(c * SEQ + bi) * 8 + h) * 2);
        mm[c] = ml.x; ll[c] = ml.y;
        M = fmaxf(M, ml.x);
    }
    float L = 0.f;
    float4 a = make_float4(0.f, 0.f, 0.f, 0.f);
#pragma unroll
    for (int c = 0; c < NCH; c++) {
        float wgt = __expf(mm[c] - M);
        L += ll[c] * wgt;
        float4 p = *(const float4*)(g_scrA + ((size_t)(c * SEQ + bi) << 9) + d0);
        a.x += p.x * wgt; a.y += p.y * wgt; a.z += p.z * wgt; a.w += p.w * wgt;
    }
    float inv = 1.0f / L;
    float o0 = a.x * inv, o1 = a.y * inv, o2 = a.z * inv, o3 = a.w * inv;
    unsigned s0, s1;
    unsigned b0 = packsplit(o0, o1, s0);
    unsigned b1 = packsplit(o2, o3, s1);
    size_t ow = (size_t)bi * 256 + (d0 >> 1);
    g_ccB[ow] = b0; g_ccB[ow + 1] = b1;
    g_ccS[ow] = s0; g_ccS[ow + 1] = s1;
}

// ---------------- launch ----------------------------------------------------
extern "C" void kernel_launch(void* const* d_in, const int* in_sizes, int n_in,
                              void* d_out, int out_size) {
    const float* x    = (const float*)d_in[0];
    const float* cbk  = (const float*)d_in[1];
    const float* cbv  = (const float*)d_in[2];
    const int*   mask = (const int*)d_in[3];
    const float* Wq = (const float*)d_in[4];
    const float* bq = (const float*)d_in[5];
    const float* Wk = (const float*)d_in[6];
    const float* bk = (const float*)d_in[7];
    const float* Wv = (const float*)d_in[8];
    const float* bv = (const float*)d_in[9];
    const float* Wo = (const float*)d_in[10];
    const float* bo = (const float*)d_in[11];
    const float* alpha1 = (const float*)d_in[12];
    const float* beta1  = (const float*)d_in[13];
    const float* alpha2 = (const float*)d_in[14];
    const float* beta2  = (const float*)d_in[15];
    const float* W1 = (const float*)d_in[16];
    const float* b1 = (const float*)d_in[17];
    const float* W2 = (const float*)d_in[18];
    const float* b2 = (const float*)d_in[19];
    float* out = (float*)d_out;

    unsigned *pyB, *pyS;
    float *py;
    cudaGetSymbolAddress((void**)&pyB, g_y2B);
    cudaGetSymbolAddress((void**)&pyS, g_y2S);
    cudaGetSymbolAddress((void**)&py,  g_y);

    // 1) prep: weight split + LN1 (one launch)
    prep_kernel<<<2048, 256>>>(Wq, Wk, Wv, Wo, W1, W2, x, alpha1, beta1);
    // 2) QKV projections, direct write with bias (384 CTAs)
    gemm_qkv_kernel<<<dim3(8, 16, 3), 128>>>(bq, bk, bv);
    // 3) attention: 4-way split-j 3-phase partials + combine
    attn_part_kernel<<<dim3(512, NCH), 128>>>(cbk, cbv, mask);
    attn_combine_kernel<<<512, 128>>>();
    // 4) Wo + bias + residual(x) -> y
    gemm_wo_kernel<<<dim3(8, 16), 128>>>(bo, x);
    // 5) LN2 -> packed split y2
    ln_split_kernel<<<512, 256>>>(py, alpha2, beta2, pyB, pyS);
    // 6) FFN up + ReLU -> packed split h
    gemm_ffn1_kernel<<<dim3(32, 16), 128>>>(b1);
    // 7) FFN down split-K=4 + reduce(+bias+residual) -> out
    gemm_ffn2_part_kernel<<<dim3(8, 16, 4), 128>>>();
    ffn2_reduce_kernel<<<512, 128>>>(b2, out);
}